// round 1
// baseline (speedup 1.0000x reference)
#include <cuda_runtime.h>
#include <math.h>
#include <stdint.h>

#define B_SZ 65536
#define Q    256
#define Q2   512
#define Q3   768
#define N_LAYERS 8

// ---------------- scratch (device globals: no runtime allocation) ----------
__device__ float g_cur[(size_t)B_SZ * Q];      // 64 MB  activation (holds residual during layer)
__device__ float g_h  [(size_t)B_SZ * Q3];     // 192 MB widest intermediate
__device__ float g_c2 [(size_t)B_SZ * Q];      // 64 MB  block output / mixed
__device__ float g_ent[(size_t)B_SZ * Q];      // 64 MB  entangled
__device__ float g_tanh_ent[N_LAYERS * Q * Q]; // 2 MB   tanh(ent[li])
__device__ float g_lin[N_LAYERS * Q];          // per-column gate linear term

// ---------------- block reduction (256 threads) ----------------------------
__device__ __forceinline__ float blockReduce256(float v) {
    __shared__ float sh[8];
    const int lane = threadIdx.x & 31, wid = threadIdx.x >> 5;
#pragma unroll
    for (int o = 16; o > 0; o >>= 1) v += __shfl_down_sync(0xffffffffu, v, o);
    __syncthreads();                 // protect sh against back-to-back calls
    if (lane == 0) sh[wid] = v;
    __syncthreads();
    if (wid == 0) {
        v = (lane < 8) ? sh[lane] : 0.f;
#pragma unroll
        for (int o = 4; o > 0; o >>= 1) v += __shfl_down_sync(0xffffffffu, v, o);
        if (lane == 0) sh[0] = v;
    }
    __syncthreads();
    return sh[0];
}

// ---------------- SGEMM: C[M x N] = act(A[M x K] @ W[K x N, ld=ldw] + bias) -
// M = 65536 always. Tiles: 128x128x16, 256 threads, 8x8 per thread.
// ACT: 0 none, 1 silu, 2 tanh.  ADD: C += scale * result.
#define BM 128
#define BN 128
#define BKT 16
#define TM 8
#define TN 8

template <int ACT, bool ADD>
__global__ __launch_bounds__(256) void sgemm_kernel(
    const float* __restrict__ A, const float* __restrict__ W,
    const float* __restrict__ bias, float* __restrict__ C,
    int N, int K, int ldw, float scale)
{
    __shared__ float As[BKT][BM];
    __shared__ float Bs[BKT][BN + 4];

    const int tid = threadIdx.x;
    const int tx = tid & 15;        // 0..15  -> N direction
    const int ty = tid >> 4;        // 0..15  -> M direction

    const float* Ab = A + (size_t)blockIdx.y * BM * K;
    const float* Wb = W + (size_t)blockIdx.x * BN;

    float acc[TM][TN];
#pragma unroll
    for (int i = 0; i < TM; i++)
#pragma unroll
        for (int j = 0; j < TN; j++) acc[i][j] = 0.f;

    for (int k0 = 0; k0 < K; k0 += BKT) {
        // A tile: 128 rows x 16 cols = 512 float4 loads, 2 per thread
#pragma unroll
        for (int it = 0; it < 2; it++) {
            int idx = tid + it * 256;          // 0..511
            int row = idx >> 2;                // 0..127
            int c4  = (idx & 3) << 2;          // 0,4,8,12
            float4 v = *(const float4*)(Ab + (size_t)row * K + k0 + c4);
            As[c4 + 0][row] = v.x;
            As[c4 + 1][row] = v.y;
            As[c4 + 2][row] = v.z;
            As[c4 + 3][row] = v.w;
        }
        // W tile: 16 rows x 128 cols = 512 float4 loads, 2 per thread
#pragma unroll
        for (int it = 0; it < 2; it++) {
            int idx = tid + it * 256;          // 0..511
            int row = idx >> 5;                // 0..15
            int col = (idx & 31) << 2;         // 0..124
            float4 v = *(const float4*)(Wb + (size_t)(k0 + row) * ldw + col);
            Bs[row][col + 0] = v.x;
            Bs[row][col + 1] = v.y;
            Bs[row][col + 2] = v.z;
            Bs[row][col + 3] = v.w;
        }
        __syncthreads();

#pragma unroll
        for (int k = 0; k < BKT; k++) {
            float a[TM], b[TN];
#pragma unroll
            for (int i = 0; i < TM; i++) a[i] = As[k][ty * TM + i];
#pragma unroll
            for (int j = 0; j < TN; j++) b[j] = Bs[k][tx * TN + j];
#pragma unroll
            for (int i = 0; i < TM; i++)
#pragma unroll
                for (int j = 0; j < TN; j++)
                    acc[i][j] = fmaf(a[i], b[j], acc[i][j]);
        }
        __syncthreads();
    }

    const size_t rowBase = (size_t)blockIdx.y * BM + ty * TM;
    const int    colBase = blockIdx.x * BN + tx * TN;
#pragma unroll
    for (int i = 0; i < TM; i++) {
        float* Crow = C + (rowBase + i) * (size_t)N + colBase;
#pragma unroll
        for (int j = 0; j < TN; j++) {
            float v = acc[i][j];
            if (bias) v += bias[colBase + j];
            if (ACT == 1) v = v / (1.f + expf(-v));   // silu
            if (ACT == 2) v = tanhf(v);
            if (ADD) Crow[j] += scale * v;
            else     Crow[j] = v;
        }
    }
}

template <int ACT, bool ADD>
static void launch_gemm(const float* A, const float* W, const float* bias,
                        float* C, int N, int K, int ldw, float scale) {
    dim3 grid(N / BN, B_SZ / BM);
    sgemm_kernel<ACT, ADD><<<grid, 256>>>(A, W, bias, C, N, K, ldw, scale);
}

// ---------------- LayerNorm + exact GELU over rows of width 768 ------------
__global__ __launch_bounds__(256) void ln_gelu_kernel(
    float* __restrict__ h, const float* __restrict__ w, const float* __restrict__ b)
{
    float* hp = h + (size_t)blockIdx.x * Q3;
    const int t = threadIdx.x;
    float v0 = hp[t], v1 = hp[t + 256], v2 = hp[t + 512];

    float s = blockReduce256(v0 + v1 + v2);
    float mu = s * (1.f / 768.f);
    float d0 = v0 - mu, d1 = v1 - mu, d2 = v2 - mu;
    float sq = blockReduce256(d0 * d0 + d1 * d1 + d2 * d2);
    float rstd = rsqrtf(sq * (1.f / 768.f) + 1e-5f);

#pragma unroll
    for (int e = 0; e < 3; e++) {
        int c = t + e * 256;
        float d = (e == 0) ? d0 : (e == 1) ? d1 : d2;
        float y = d * rstd * w[c] + b[c];
        // exact gelu: 0.5 * y * (1 + erf(y / sqrt(2)))
        y = 0.5f * y * (1.f + erff(y * 0.70710678118654752f));
        hp[c] = y;
    }
}

// ---------------- gate + entangle mix (in-place on g_c2) -------------------
__global__ __launch_bounds__(256) void combine_kernel(const float* __restrict__ gp, int li)
{
    size_t idx = (size_t)blockIdx.x * 256 + threadIdx.x;
    int q = (int)(idx & (Q - 1));
    float c = g_c2[idx];
    float e = g_ent[idx];
    float lin = g_lin[li * Q + q];
    const float* p = gp + (size_t)li * Q * 6 + q * 6;
    float gate = (lin * c + 0.5f * sinf(p[3] * c + p[4]) + 0.5f * cosf(p[5] * c)) * 0.25f;
    g_c2[idx] = (c + 0.3f * gate + 0.2f * e) * (1.f / 1.5f);
}

// ---------------- residual mix + row L2 norm + tanh ------------------------
__global__ __launch_bounds__(256) void finalize_kernel(
    const float* __restrict__ res, float* __restrict__ out, float alpha)
{
    size_t idx = (size_t)blockIdx.x * Q + threadIdx.x;
    float v = alpha * g_c2[idx] + (1.f - alpha) * res[idx];
    float sq = blockReduce256(v * v);
    float nrm = sqrtf(sq) + 1e-8f;
    out[idx] = tanhf(v / nrm);
}

// ---------------- per-call weight precompute -------------------------------
__global__ void prep_tanh_ent(const float* __restrict__ ent) {
    int idx = blockIdx.x * 256 + threadIdx.x;       // N_LAYERS*Q*Q total
    g_tanh_ent[idx] = tanhf(ent[idx]);
}

__global__ void prep_lin(const float* __restrict__ gp) {
    int idx = blockIdx.x * 256 + threadIdx.x;       // N_LAYERS*Q total
    int li = idx / Q, q = idx % Q;
    const float* p = gp + (size_t)li * Q * 6 + q * 6;
    g_lin[idx] = sinf(p[0]) + cosf(p[1]) + tanhf(p[2]);
}

// ---------------- orchestration --------------------------------------------
extern "C" void kernel_launch(void* const* d_in, const int* in_sizes, int n_in,
                              void* d_out, int out_size)
{
    const float* x    = (const float*)d_in[0];
    const float* d0w1 = (const float*)d_in[1];
    const float* d0b1 = (const float*)d_in[2];
    const float* lnw  = (const float*)d_in[3];
    const float* lnb  = (const float*)d_in[4];
    const float* d0w2 = (const float*)d_in[5];
    const float* d0b2 = (const float*)d_in[6];
    const float* d1w1 = (const float*)d_in[7];
    const float* d1b1 = (const float*)d_in[8];
    const float* d1w2 = (const float*)d_in[9];
    const float* d1b2 = (const float*)d_in[10];
    const float* wqkv = (const float*)d_in[11];
    const float* bqkv = (const float*)d_in[12];
    const float* wo   = (const float*)d_in[13];
    const float* bo   = (const float*)d_in[14];
    const float* gp   = (const float*)d_in[15];
    const float* ent  = (const float*)d_in[16];
    const float* nlw1 = (const float*)d_in[17];
    const float* nlb1 = (const float*)d_in[18];
    const float* nlw2 = (const float*)d_in[19];
    const float* nlb2 = (const float*)d_in[20];
    float* out = (float*)d_out;

    float *cur, *h, *c2, *entb, *te;
    cudaGetSymbolAddress((void**)&cur,  g_cur);
    cudaGetSymbolAddress((void**)&h,    g_h);
    cudaGetSymbolAddress((void**)&c2,   g_c2);
    cudaGetSymbolAddress((void**)&entb, g_ent);
    cudaGetSymbolAddress((void**)&te,   g_tanh_ent);

    prep_tanh_ent<<<N_LAYERS * Q * Q / 256, 256>>>(ent);
    prep_lin<<<N_LAYERS * Q / 256, 256>>>(gp);

    for (int li = 0; li < N_LAYERS; li++) {
        const float* in = (li == 0) ? x : cur;
        const int t = li % 3;

        if (t == 0) {
            int i = li / 3;
            launch_gemm<0, false>(in, d0w1 + (size_t)i * Q * Q3, d0b1 + i * Q3, h, Q3, Q, Q3, 0.f);
            ln_gelu_kernel<<<B_SZ, 256>>>(h, lnw + i * Q3, lnb + i * Q3);
            launch_gemm<0, false>(h, d0w2 + (size_t)i * Q3 * Q, d0b2 + i * Q, c2, Q, Q3, Q, 0.f);
        } else if (t == 1) {
            int i = (li - 1) / 3;
            launch_gemm<1, false>(in, d1w1 + (size_t)i * Q * Q2, d1b1 + i * Q2, h, Q2, Q, Q2, 0.f);
            launch_gemm<0, false>(h, d1w2 + (size_t)i * Q2 * Q, d1b2 + i * Q, c2, Q, Q2, Q, 0.f);
        } else {
            int i = (li - 2) / 3;
            // only the V slice of qkv is used: columns [2Q, 3Q)
            launch_gemm<0, false>(in, wqkv + (size_t)i * Q * Q3 + 2 * Q, bqkv + i * Q3 + 2 * Q,
                                  h, Q, Q, Q3, 0.f);
            launch_gemm<0, false>(h, wo + (size_t)i * Q * Q, bo + i * Q, c2, Q, Q, Q, 0.f);
        }

        // entangled = c2 @ tanh(ent[li])   (must read c2 before combine overwrites it)
        launch_gemm<0, false>(c2, te + (size_t)li * Q * Q, nullptr, entb, Q, Q, Q, 0.f);
        combine_kernel<<<B_SZ * Q / 256, 256>>>(gp, li);

        if (li & 1) {
            int j = li / 2;
            launch_gemm<2, false>(c2, nlw1 + (size_t)j * Q * Q, nlb1 + j * Q, h, Q, Q, Q, 0.f);
            launch_gemm<0, true >(h, nlw2 + (size_t)j * Q * Q, nlb2 + j * Q, c2, Q, Q, Q, 0.1f);
        }

        float alpha = (li < N_LAYERS / 2) ? 0.8f : 0.6f;
        finalize_kernel<<<B_SZ, 256>>>((li == 0) ? x : cur, (li == 7) ? out : cur, alpha);
    }
}

// round 2
// speedup vs baseline: 1.6755x; 1.6755x over previous
#include <cuda_runtime.h>
#include <cuda_bf16.h>
#include <math.h>
#include <stdint.h>

#define B_SZ 65536
#define Q    256
#define Q2   512
#define Q3   768
#define N_LAYERS 8

typedef __nv_bfloat16 bf16;

// ---------------- fp32 scratch ----------------------------------------------
__device__ __align__(128) float g_cur[(size_t)B_SZ * Q];
__device__ __align__(128) float g_h  [(size_t)B_SZ * Q3];
__device__ __align__(128) float g_c2 [(size_t)B_SZ * Q];
__device__ __align__(128) float g_ent[(size_t)B_SZ * Q];
__device__ float g_lin[N_LAYERS * Q];

// ---------------- bf16 split scratch (activations) ---------------------------
__device__ __align__(128) bf16 s_curhi[(size_t)B_SZ * Q];
__device__ __align__(128) bf16 s_curlo[(size_t)B_SZ * Q];
__device__ __align__(128) bf16 s_hhi  [(size_t)B_SZ * Q3];
__device__ __align__(128) bf16 s_hlo  [(size_t)B_SZ * Q3];
__device__ __align__(128) bf16 s_c2hi [(size_t)B_SZ * Q];
__device__ __align__(128) bf16 s_c2lo [(size_t)B_SZ * Q];

// ---------------- bf16 split scratch (weights) -------------------------------
__device__ __align__(128) bf16 w0a_hi[3 * Q * Q3], w0a_lo[3 * Q * Q3];
__device__ __align__(128) bf16 w0b_hi[3 * Q3 * Q], w0b_lo[3 * Q3 * Q];
__device__ __align__(128) bf16 w1a_hi[3 * Q * Q2], w1a_lo[3 * Q * Q2];
__device__ __align__(128) bf16 w1b_hi[3 * Q2 * Q], w1b_lo[3 * Q2 * Q];
__device__ __align__(128) bf16 wv_hi [2 * Q * Q],  wv_lo [2 * Q * Q];
__device__ __align__(128) bf16 wo_hi [2 * Q * Q],  wo_lo [2 * Q * Q];
__device__ __align__(128) bf16 we_hi [N_LAYERS * Q * Q], we_lo[N_LAYERS * Q * Q];
__device__ __align__(128) bf16 wn1_hi[4 * Q * Q],  wn1_lo[4 * Q * Q];
__device__ __align__(128) bf16 wn2_hi[4 * Q * Q],  wn2_lo[4 * Q * Q];

// ---------------- helpers ----------------------------------------------------
__device__ __forceinline__ void split2(float v, bf16& hi, bf16& lo) {
    hi = __float2bfloat16(v);
    lo = __float2bfloat16(v - __bfloat162float(hi));
}

__device__ __forceinline__ float blockReduce256(float v) {
    __shared__ float sh[8];
    const int lane = threadIdx.x & 31, wid = threadIdx.x >> 5;
#pragma unroll
    for (int o = 16; o > 0; o >>= 1) v += __shfl_down_sync(0xffffffffu, v, o);
    __syncthreads();
    if (lane == 0) sh[wid] = v;
    __syncthreads();
    if (wid == 0) {
        v = (lane < 8) ? sh[lane] : 0.f;
#pragma unroll
        for (int o = 4; o > 0; o >>= 1) v += __shfl_down_sync(0xffffffffu, v, o);
        if (lane == 0) sh[0] = v;
    }
    __syncthreads();
    return sh[0];
}

__device__ __forceinline__ void mma16816(float* c, const uint32_t* a, const uint32_t* b) {
    asm volatile(
        "mma.sync.aligned.m16n8k16.row.col.f32.bf16.bf16.f32 "
        "{%0,%1,%2,%3}, {%4,%5,%6,%7}, {%8,%9}, {%0,%1,%2,%3};\n"
        : "+f"(c[0]), "+f"(c[1]), "+f"(c[2]), "+f"(c[3])
        : "r"(a[0]), "r"(a[1]), "r"(a[2]), "r"(a[3]), "r"(b[0]), "r"(b[1]));
}

// ---------------- split-bf16 3-term tensor-core GEMM -------------------------
// C[M x N] = act( (Ah+Al)[M x K] @ (Bh+Bl)[K x N] + bias ), 3 mma passes fused
// as a virtual-K loop:  part 0: Ah*Bh, part 1: Al*Bh, part 2: Ah*Bl.
// BM=128, BN=128, BK=32, 256 threads, warp grid 2x4, 64x32 per warp.
// ACT: 0 none, 1 silu, 2 tanh.
// OUT: 0 f32 only | 1 splits only | 2 f32+splits | 3 f32 += scale*v.
#define BMT 128
#define BNT 128
#define BKT 32
#define RSA 20   // A smem row stride in words ((32+8)*2B/4B)
#define RSB 136  // B smem k-pair row stride in words (128 + 8 pad)

template <int ACT, int OUT>
__global__ __launch_bounds__(256) void mma_gemm(
    const bf16* __restrict__ Ahi, const bf16* __restrict__ Alo,
    const bf16* __restrict__ Whi, const bf16* __restrict__ Wlo,
    const float* __restrict__ bias,
    float* __restrict__ Cf, bf16* __restrict__ Chi, bf16* __restrict__ Clo,
    int N, int K, float scale)
{
    __shared__ uint32_t sA[2][BMT * RSA];
    __shared__ uint32_t sB[2][16 * RSB];

    const int tid  = threadIdx.x;
    const int warp = tid >> 5, lane = tid & 31;
    const int warpM = warp >> 2, warpN = warp & 3;
    const int g = lane >> 2, t = lane & 3;

    const int    bn = blockIdx.x * BNT;
    const size_t bm = (size_t)blockIdx.y * BMT;

    const bf16* Aparts[3] = {Ahi, Alo, Ahi};
    const bf16* Bparts[3] = {Whi, Whi, Wlo};

    const int kt_per_part = K / BKT;
    const int KT = 3 * kt_per_part;

    float acc[4][4][4];
#pragma unroll
    for (int i = 0; i < 4; i++)
#pragma unroll
        for (int j = 0; j < 4; j++)
#pragma unroll
            for (int c = 0; c < 4; c++) acc[i][j][c] = 0.f;

    // staging geometry
    const int a_row = tid >> 2;            // 0..63 (+64 for second half)
    const int a_kw4 = tid & 3;             // which 8-elem k group
    const int b_kp  = tid >> 4;            // 0..15 k-pair
    const int b_n8  = (tid & 15) * 8;      // n offset

    uint4 av0, av1, bw0, bw1;

    auto ldg_tiles = [&](int kt) {
        int p  = kt / kt_per_part;
        int kk = (kt - p * kt_per_part) * BKT;
        const bf16* As = Aparts[p] + (bm + a_row) * K + kk + a_kw4 * 8;
        av0 = *(const uint4*)As;
        av1 = *(const uint4*)(As + (size_t)64 * K);
        const bf16* Bs = Bparts[p] + (size_t)(kk + 2 * b_kp) * N + bn + b_n8;
        bw0 = *(const uint4*)Bs;
        bw1 = *(const uint4*)(Bs + N);
    };
    auto sts_tiles = [&](int buf) {
        *(uint4*)&sA[buf][a_row * RSA + a_kw4 * 4]        = av0;
        *(uint4*)&sA[buf][(a_row + 64) * RSA + a_kw4 * 4] = av1;
        uint32_t* d = &sB[buf][b_kp * RSB + b_n8];
        uint4 o0, o1;
        o0.x = __byte_perm(bw0.x, bw1.x, 0x5410); o0.y = __byte_perm(bw0.x, bw1.x, 0x7632);
        o0.z = __byte_perm(bw0.y, bw1.y, 0x5410); o0.w = __byte_perm(bw0.y, bw1.y, 0x7632);
        o1.x = __byte_perm(bw0.z, bw1.z, 0x5410); o1.y = __byte_perm(bw0.z, bw1.z, 0x7632);
        o1.z = __byte_perm(bw0.w, bw1.w, 0x5410); o1.w = __byte_perm(bw0.w, bw1.w, 0x7632);
        *(uint4*)&d[0] = o0;
        *(uint4*)&d[4] = o1;
    };

    ldg_tiles(0);
    sts_tiles(0);
    __syncthreads();

    for (int kt = 0; kt < KT; kt++) {
        const int buf = kt & 1;
        if (kt + 1 < KT) ldg_tiles(kt + 1);

        const uint32_t* pA = sA[buf];
        const uint32_t* pB = sB[buf];
#pragma unroll
        for (int ks = 0; ks < 2; ks++) {
            uint32_t af[4][4], bfr[4][2];
#pragma unroll
            for (int mi = 0; mi < 4; mi++) {
                int row = warpM * 64 + mi * 16 + g;
                af[mi][0] = pA[row * RSA + ks * 8 + t];
                af[mi][1] = pA[(row + 8) * RSA + ks * 8 + t];
                af[mi][2] = pA[row * RSA + ks * 8 + t + 4];
                af[mi][3] = pA[(row + 8) * RSA + ks * 8 + t + 4];
            }
#pragma unroll
            for (int ni = 0; ni < 4; ni++) {
                int col = warpN * 32 + ni * 8 + g;
                bfr[ni][0] = pB[(ks * 8 + t) * RSB + col];
                bfr[ni][1] = pB[(ks * 8 + t + 4) * RSB + col];
            }
#pragma unroll
            for (int mi = 0; mi < 4; mi++)
#pragma unroll
                for (int ni = 0; ni < 4; ni++)
                    mma16816(acc[mi][ni], af[mi], bfr[ni]);
        }
        if (kt + 1 < KT) sts_tiles((kt + 1) & 1);
        __syncthreads();
    }

    // epilogue
#pragma unroll
    for (int mi = 0; mi < 4; mi++) {
        size_t r0 = bm + warpM * 64 + mi * 16 + g;
#pragma unroll
        for (int ni = 0; ni < 4; ni++) {
            int col = bn + warpN * 32 + ni * 8 + 2 * t;
            float b0 = 0.f, b1 = 0.f;
            if (bias) { b0 = bias[col]; b1 = bias[col + 1]; }
#pragma unroll
            for (int half = 0; half < 2; half++) {
                size_t r = r0 + half * 8;
                float v0 = acc[mi][ni][half * 2 + 0] + b0;
                float v1 = acc[mi][ni][half * 2 + 1] + b1;
                if (ACT == 1) { v0 = v0 / (1.f + expf(-v0)); v1 = v1 / (1.f + expf(-v1)); }
                if (ACT == 2) { v0 = tanhf(v0); v1 = tanhf(v1); }
                size_t idx = r * (size_t)N + col;
                if (OUT == 0 || OUT == 2) { *(float2*)&Cf[idx] = make_float2(v0, v1); }
                if (OUT == 3) { Cf[idx] += scale * v0; Cf[idx + 1] += scale * v1; }
                if (OUT == 1 || OUT == 2) {
                    bf16 h0, l0, h1, l1;
                    split2(v0, h0, l0); split2(v1, h1, l1);
                    *(__nv_bfloat162*)&Chi[idx] = __nv_bfloat162(h0, h1);
                    *(__nv_bfloat162*)&Clo[idx] = __nv_bfloat162(l0, l1);
                }
            }
        }
    }
}

template <int ACT, int OUT>
static void launch_mma(const bf16* Ahi, const bf16* Alo,
                       const bf16* Whi, const bf16* Wlo, const float* bias,
                       float* Cf, bf16* Chi, bf16* Clo, int N, int K, float scale = 0.f)
{
    dim3 grid(N / BNT, B_SZ / BMT);
    mma_gemm<ACT, OUT><<<grid, 256>>>(Ahi, Alo, Whi, Wlo, bias, Cf, Chi, Clo, N, K, scale);
}

// ---------------- LayerNorm + exact GELU (row width 768) -> splits -----------
__global__ __launch_bounds__(256) void ln_gelu_kernel(
    const float* __restrict__ h, const float* __restrict__ w, const float* __restrict__ b,
    bf16* __restrict__ hhi, bf16* __restrict__ hlo)
{
    const size_t base = (size_t)blockIdx.x * Q3;
    const int t = threadIdx.x;
    float v0 = h[base + t], v1 = h[base + t + 256], v2 = h[base + t + 512];

    float s = blockReduce256(v0 + v1 + v2);
    float mu = s * (1.f / 768.f);
    float d0 = v0 - mu, d1 = v1 - mu, d2 = v2 - mu;
    float sq = blockReduce256(d0 * d0 + d1 * d1 + d2 * d2);
    float rstd = rsqrtf(sq * (1.f / 768.f) + 1e-5f);

#pragma unroll
    for (int e = 0; e < 3; e++) {
        int c = t + e * 256;
        float d = (e == 0) ? d0 : (e == 1) ? d1 : d2;
        float y = d * rstd * w[c] + b[c];
        y = 0.5f * y * (1.f + erff(y * 0.70710678118654752f));
        bf16 hi, lo; split2(y, hi, lo);
        hhi[base + c] = hi; hlo[base + c] = lo;
    }
}

// ---------------- gate + entangle mix ----------------------------------------
template <bool SPLIT>
__global__ __launch_bounds__(256) void combine_kernel(const float* __restrict__ gp, int li)
{
    size_t idx = (size_t)blockIdx.x * 256 + threadIdx.x;
    int q = (int)(idx & (Q - 1));
    float c = g_c2[idx];
    float e = g_ent[idx];
    float lin = g_lin[li * Q + q];
    const float* p = gp + (size_t)li * Q * 6 + q * 6;
    float gate = (lin * c + 0.5f * sinf(p[3] * c + p[4]) + 0.5f * cosf(p[5] * c)) * 0.25f;
    float out = (c + 0.3f * gate + 0.2f * e) * (1.f / 1.5f);
    g_c2[idx] = out;
    if (SPLIT) {
        bf16 hi, lo; split2(out, hi, lo);
        s_c2hi[idx] = hi; s_c2lo[idx] = lo;
    }
}

// ---------------- residual mix + row L2 norm + tanh + splits -----------------
__global__ __launch_bounds__(256) void finalize_kernel(
    const float* __restrict__ res, float* __restrict__ out, float alpha, int write_split)
{
    size_t idx = (size_t)blockIdx.x * Q + threadIdx.x;
    float v = alpha * g_c2[idx] + (1.f - alpha) * res[idx];
    float sq = blockReduce256(v * v);
    float nrm = sqrtf(sq) + 1e-8f;
    float y = tanhf(v / nrm);
    out[idx] = y;
    if (write_split) {
        bf16 hi, lo; split2(y, hi, lo);
        s_curhi[idx] = hi; s_curlo[idx] = lo;
    }
}

// ---------------- per-call precompute ----------------------------------------
__global__ void split_plain(const float* __restrict__ src, bf16* __restrict__ hi,
                            bf16* __restrict__ lo) {
    size_t idx = (size_t)blockIdx.x * 256 + threadIdx.x;
    bf16 h, l; split2(src[idx], h, l);
    hi[idx] = h; lo[idx] = l;
}

__global__ void split_tanh(const float* __restrict__ src, bf16* __restrict__ hi,
                           bf16* __restrict__ lo) {
    size_t idx = (size_t)blockIdx.x * 256 + threadIdx.x;
    bf16 h, l; split2(tanhf(src[idx]), h, l);
    hi[idx] = h; lo[idx] = l;
}

__global__ void split_vslice(const float* __restrict__ wqkv, bf16* __restrict__ hi,
                             bf16* __restrict__ lo) {
    int idx = blockIdx.x * 256 + threadIdx.x;     // 2*Q*Q
    int i = idx >> 16, rem = idx & 65535;
    int k = rem >> 8, c = rem & 255;
    float v = wqkv[(size_t)i * Q * Q3 + (size_t)k * Q3 + 2 * Q + c];
    bf16 h, l; split2(v, h, l);
    hi[idx] = h; lo[idx] = l;
}

__global__ void prep_lin(const float* __restrict__ gp) {
    int idx = blockIdx.x * 256 + threadIdx.x;     // N_LAYERS*Q
    int li = idx / Q, q = idx % Q;
    const float* p = gp + (size_t)li * Q * 6 + q * 6;
    g_lin[idx] = sinf(p[0]) + cosf(p[1]) + tanhf(p[2]);
}

// ---------------- orchestration ----------------------------------------------
extern "C" void kernel_launch(void* const* d_in, const int* in_sizes, int n_in,
                              void* d_out, int out_size)
{
    const float* x    = (const float*)d_in[0];
    const float* d0b1 = (const float*)d_in[2];
    const float* lnw  = (const float*)d_in[3];
    const float* lnb  = (const float*)d_in[4];
    const float* d0b2 = (const float*)d_in[6];
    const float* d1b1 = (const float*)d_in[8];
    const float* d1b2 = (const float*)d_in[10];
    const float* bqkv = (const float*)d_in[12];
    const float* bo   = (const float*)d_in[14];
    const float* gp   = (const float*)d_in[15];
    const float* nlb1 = (const float*)d_in[18];
    const float* nlb2 = (const float*)d_in[20];
    float* out = (float*)d_out;

    float *cur, *h, *c2, *entb;
    cudaGetSymbolAddress((void**)&cur,  g_cur);
    cudaGetSymbolAddress((void**)&h,    g_h);
    cudaGetSymbolAddress((void**)&c2,   g_c2);
    cudaGetSymbolAddress((void**)&entb, g_ent);

    bf16 *curhi, *curlo, *hhi, *hlo, *c2hi, *c2lo;
    cudaGetSymbolAddress((void**)&curhi, s_curhi);
    cudaGetSymbolAddress((void**)&curlo, s_curlo);
    cudaGetSymbolAddress((void**)&hhi,   s_hhi);
    cudaGetSymbolAddress((void**)&hlo,   s_hlo);
    cudaGetSymbolAddress((void**)&c2hi,  s_c2hi);
    cudaGetSymbolAddress((void**)&c2lo,  s_c2lo);

    bf16 *p_w0a_hi, *p_w0a_lo, *p_w0b_hi, *p_w0b_lo, *p_w1a_hi, *p_w1a_lo,
         *p_w1b_hi, *p_w1b_lo, *p_wv_hi, *p_wv_lo, *p_wo_hi, *p_wo_lo,
         *p_we_hi, *p_we_lo, *p_wn1_hi, *p_wn1_lo, *p_wn2_hi, *p_wn2_lo;
    cudaGetSymbolAddress((void**)&p_w0a_hi, w0a_hi); cudaGetSymbolAddress((void**)&p_w0a_lo, w0a_lo);
    cudaGetSymbolAddress((void**)&p_w0b_hi, w0b_hi); cudaGetSymbolAddress((void**)&p_w0b_lo, w0b_lo);
    cudaGetSymbolAddress((void**)&p_w1a_hi, w1a_hi); cudaGetSymbolAddress((void**)&p_w1a_lo, w1a_lo);
    cudaGetSymbolAddress((void**)&p_w1b_hi, w1b_hi); cudaGetSymbolAddress((void**)&p_w1b_lo, w1b_lo);
    cudaGetSymbolAddress((void**)&p_wv_hi,  wv_hi);  cudaGetSymbolAddress((void**)&p_wv_lo,  wv_lo);
    cudaGetSymbolAddress((void**)&p_wo_hi,  wo_hi);  cudaGetSymbolAddress((void**)&p_wo_lo,  wo_lo);
    cudaGetSymbolAddress((void**)&p_we_hi,  we_hi);  cudaGetSymbolAddress((void**)&p_we_lo,  we_lo);
    cudaGetSymbolAddress((void**)&p_wn1_hi, wn1_hi); cudaGetSymbolAddress((void**)&p_wn1_lo, wn1_lo);
    cudaGetSymbolAddress((void**)&p_wn2_hi, wn2_hi); cudaGetSymbolAddress((void**)&p_wn2_lo, wn2_lo);

    // weight prep (cheap, once per call)
    split_plain<<<3 * Q * Q3 / 256, 256>>>((const float*)d_in[1], p_w0a_hi, p_w0a_lo);
    split_plain<<<3 * Q3 * Q / 256, 256>>>((const float*)d_in[5], p_w0b_hi, p_w0b_lo);
    split_plain<<<3 * Q * Q2 / 256, 256>>>((const float*)d_in[7], p_w1a_hi, p_w1a_lo);
    split_plain<<<3 * Q2 * Q / 256, 256>>>((const float*)d_in[9], p_w1b_hi, p_w1b_lo);
    split_vslice<<<2 * Q * Q / 256, 256>>>((const float*)d_in[11], p_wv_hi, p_wv_lo);
    split_plain<<<2 * Q * Q / 256, 256>>>((const float*)d_in[13], p_wo_hi, p_wo_lo);
    split_tanh<<<N_LAYERS * Q * Q / 256, 256>>>((const float*)d_in[16], p_we_hi, p_we_lo);
    split_plain<<<4 * Q * Q / 256, 256>>>((const float*)d_in[17], p_wn1_hi, p_wn1_lo);
    split_plain<<<4 * Q * Q / 256, 256>>>((const float*)d_in[19], p_wn2_hi, p_wn2_lo);
    prep_lin<<<N_LAYERS * Q / 256, 256>>>(gp);

    // split input x into cur splits
    split_plain<<<(size_t)B_SZ * Q / 256, 256>>>(x, curhi, curlo);

    for (int li = 0; li < N_LAYERS; li++) {
        const int t = li % 3;

        if (t == 0) {
            int i = li / 3;
            launch_mma<0, 0>(curhi, curlo, p_w0a_hi + (size_t)i * Q * Q3, p_w0a_lo + (size_t)i * Q * Q3,
                             d0b1 + i * Q3, h, nullptr, nullptr, Q3, Q);
            ln_gelu_kernel<<<B_SZ, 256>>>(h, lnw + i * Q3, lnb + i * Q3, hhi, hlo);
            launch_mma<0, 2>(hhi, hlo, p_w0b_hi + (size_t)i * Q3 * Q, p_w0b_lo + (size_t)i * Q3 * Q,
                             d0b2 + i * Q, c2, c2hi, c2lo, Q, Q3);
        } else if (t == 1) {
            int i = (li - 1) / 3;
            launch_mma<1, 1>(curhi, curlo, p_w1a_hi + (size_t)i * Q * Q2, p_w1a_lo + (size_t)i * Q * Q2,
                             d1b1 + i * Q2, nullptr, hhi, hlo, Q2, Q);
            launch_mma<0, 2>(hhi, hlo, p_w1b_hi + (size_t)i * Q2 * Q, p_w1b_lo + (size_t)i * Q2 * Q,
                             d1b2 + i * Q, c2, c2hi, c2lo, Q, Q2);
        } else {
            int i = (li - 2) / 3;
            launch_mma<0, 1>(curhi, curlo, p_wv_hi + (size_t)i * Q * Q, p_wv_lo + (size_t)i * Q * Q,
                             bqkv + i * Q3 + 2 * Q, nullptr, hhi, hlo, Q, Q);
            launch_mma<0, 2>(hhi, hlo, p_wo_hi + (size_t)i * Q * Q, p_wo_lo + (size_t)i * Q * Q,
                             bo + i * Q, c2, c2hi, c2lo, Q, Q);
        }

        // entangled = c2 @ tanh(ent[li])
        launch_mma<0, 0>(c2hi, c2lo, p_we_hi + (size_t)li * Q * Q, p_we_lo + (size_t)li * Q * Q,
                         nullptr, entb, nullptr, nullptr, Q, Q);

        if (li & 1) combine_kernel<true ><<<(size_t)B_SZ * Q / 256, 256>>>(gp, li);
        else        combine_kernel<false><<<(size_t)B_SZ * Q / 256, 256>>>(gp, li);

        if (li & 1) {
            int j = li / 2;
            launch_mma<2, 1>(c2hi, c2lo, p_wn1_hi + (size_t)j * Q * Q, p_wn1_lo + (size_t)j * Q * Q,
                             nlb1 + j * Q, nullptr, hhi, hlo, Q, Q);
            launch_mma<0, 3>(hhi, hlo, p_wn2_hi + (size_t)j * Q * Q, p_wn2_lo + (size_t)j * Q * Q,
                             nlb2 + j * Q, c2, nullptr, nullptr, Q, Q, 0.1f);
        }

        float alpha = (li < N_LAYERS / 2) ? 0.8f : 0.6f;
        finalize_kernel<<<B_SZ, 256>>>((li == 0) ? x : cur, (li == 7) ? out : cur,
                                       alpha, (li == 7) ? 0 : 1);
    }
}

// round 7
// speedup vs baseline: 1.7210x; 1.0272x over previous
#include <cuda_runtime.h>
#include <cuda_bf16.h>
#include <math.h>
#include <stdint.h>

#define B_SZ 65536
#define Q    256
#define Q2   512
#define Q3   768
#define N_LAYERS 8

typedef __nv_bfloat16 bf16;

// ---------------- fp32 scratch ----------------------------------------------
__device__ __align__(128) float g_cur[(size_t)B_SZ * Q];
__device__ __align__(128) float g_h  [(size_t)B_SZ * Q3];
__device__ __align__(128) float g_c2 [(size_t)B_SZ * Q];
__device__ float g_lin[N_LAYERS * Q];

// ---------------- bf16 split scratch (activations) ---------------------------
__device__ __align__(128) bf16 s_curhi[(size_t)B_SZ * Q];
__device__ __align__(128) bf16 s_curlo[(size_t)B_SZ * Q];
__device__ __align__(128) bf16 s_hhi  [(size_t)B_SZ * Q3];
__device__ __align__(128) bf16 s_hlo  [(size_t)B_SZ * Q3];
__device__ __align__(128) bf16 s_c2hi [(size_t)B_SZ * Q];
__device__ __align__(128) bf16 s_c2lo [(size_t)B_SZ * Q];
__device__ __align__(128) bf16 s_c3hi [(size_t)B_SZ * Q];
__device__ __align__(128) bf16 s_c3lo [(size_t)B_SZ * Q];

// ---------------- bf16 split weights ([K][N] natural layout) -----------------
__device__ __align__(128) bf16 w0a_hi[3 * Q * Q3], w0a_lo[3 * Q * Q3];
__device__ __align__(128) bf16 w0b_hi[3 * Q3 * Q], w0b_lo[3 * Q3 * Q];
__device__ __align__(128) bf16 w1a_hi[3 * Q * Q2], w1a_lo[3 * Q * Q2];
__device__ __align__(128) bf16 w1b_hi[3 * Q2 * Q], w1b_lo[3 * Q2 * Q];
__device__ __align__(128) bf16 wv_hi [2 * Q * Q],  wv_lo [2 * Q * Q];
__device__ __align__(128) bf16 wo_hi [2 * Q * Q],  wo_lo [2 * Q * Q];
__device__ __align__(128) bf16 we_hi [N_LAYERS * Q * Q], we_lo[N_LAYERS * Q * Q];
__device__ __align__(128) bf16 wn1_hi[4 * Q * Q],  wn1_lo[4 * Q * Q];
__device__ __align__(128) bf16 wn2_hi[4 * Q * Q],  wn2_lo[4 * Q * Q];

// ---------------- helpers ----------------------------------------------------
__device__ __forceinline__ void split2(float v, bf16& hi, bf16& lo) {
    hi = __float2bfloat16(v);
    lo = __float2bfloat16(v - __bfloat162float(hi));
}

__device__ __forceinline__ float blockReduce256(float v) {
    __shared__ float sh[8];
    const int lane = threadIdx.x & 31, wid = threadIdx.x >> 5;
#pragma unroll
    for (int o = 16; o > 0; o >>= 1) v += __shfl_down_sync(0xffffffffu, v, o);
    __syncthreads();
    if (lane == 0) sh[wid] = v;
    __syncthreads();
    if (wid == 0) {
        v = (lane < 8) ? sh[lane] : 0.f;
#pragma unroll
        for (int o = 4; o > 0; o >>= 1) v += __shfl_down_sync(0xffffffffu, v, o);
        if (lane == 0) sh[0] = v;
    }
    __syncthreads();
    return sh[0];
}

__device__ __forceinline__ void mma16816(float* c, const uint32_t* a, const uint32_t* b) {
    asm volatile(
        "mma.sync.aligned.m16n8k16.row.col.f32.bf16.bf16.f32 "
        "{%0,%1,%2,%3}, {%4,%5,%6,%7}, {%8,%9}, {%0,%1,%2,%3};\n"
        : "+f"(c[0]), "+f"(c[1]), "+f"(c[2]), "+f"(c[3])
        : "r"(a[0]), "r"(a[1]), "r"(a[2]), "r"(a[3]), "r"(b[0]), "r"(b[1]));
}

// ---------------- split-bf16 3-term tensor-core GEMM -------------------------
// C[M x N] = act( (Ah+Al)[M x K] @ (Bh+Bl)[K x N] + bias ), virtual-K loop:
// part 0: Ah*Bh, part 1: Al*Bh, part 2: Ah*Bl.
// BM=128, BN=128, BK=32, 256 threads, warp grid 2x4, 64x32 per warp.
// ACT: 0 none, 1 silu, 2 tanh.
// OUT: 0 f32 | 1 splits | 2 f32+splits | 3 f32 += scale*v
//      4 combine(gate+entangle) in-place on Cf | 5 combine + splits.
#define BMT 128
#define BNT 128
#define BKT 32
#define RSA 20   // A smem row stride in words
#define RSB 136  // B smem k-pair row stride in words

template <int ACT, int OUT>
__global__ __launch_bounds__(256) void mma_gemm(
    const bf16* __restrict__ Ahi, const bf16* __restrict__ Alo,
    const bf16* __restrict__ Whi, const bf16* __restrict__ Wlo,
    const float* __restrict__ bias,
    float* __restrict__ Cf, bf16* __restrict__ Chi, bf16* __restrict__ Clo,
    int N, int K, float scale, const float* __restrict__ gparams, int li)
{
    __shared__ uint32_t sA[2][BMT * RSA];
    __shared__ uint32_t sB[2][16 * RSB];

    const int tid = threadIdx.x;
    const int warp = tid >> 5, lane = tid & 31;
    const int warpM = warp >> 2, warpN = warp & 3;
    const int g = lane >> 2, t = lane & 3;

    const int    bn = blockIdx.x * BNT;
    const size_t bm = (size_t)blockIdx.y * BMT;

    const bf16* Aparts[3] = {Ahi, Alo, Ahi};
    const bf16* Bparts[3] = {Whi, Whi, Wlo};

    const int kt_per_part = K / BKT;
    const int KT = 3 * kt_per_part;

    float acc[4][4][4];
#pragma unroll
    for (int i = 0; i < 4; i++)
#pragma unroll
        for (int j = 0; j < 4; j++)
#pragma unroll
            for (int c = 0; c < 4; c++) acc[i][j][c] = 0.f;

    const int a_row = tid >> 2;
    const int a_kw4 = tid & 3;
    const int b_kp  = tid >> 4;
    const int b_n8  = (tid & 15) * 8;

    uint4 av0, av1, bw0, bw1;

    auto ldg_tiles = [&](int kt) {
        int p  = kt / kt_per_part;
        int kk = (kt - p * kt_per_part) * BKT;
        const bf16* As = Aparts[p] + (bm + a_row) * K + kk + a_kw4 * 8;
        av0 = *(const uint4*)As;
        av1 = *(const uint4*)(As + (size_t)64 * K);
        const bf16* Bs = Bparts[p] + (size_t)(kk + 2 * b_kp) * N + bn + b_n8;
        bw0 = *(const uint4*)Bs;
        bw1 = *(const uint4*)(Bs + N);
    };
    auto sts_tiles = [&](int buf) {
        *(uint4*)&sA[buf][a_row * RSA + a_kw4 * 4]        = av0;
        *(uint4*)&sA[buf][(a_row + 64) * RSA + a_kw4 * 4] = av1;
        uint32_t* d = &sB[buf][b_kp * RSB + b_n8];
        uint4 o0, o1;
        o0.x = __byte_perm(bw0.x, bw1.x, 0x5410); o0.y = __byte_perm(bw0.x, bw1.x, 0x7632);
        o0.z = __byte_perm(bw0.y, bw1.y, 0x5410); o0.w = __byte_perm(bw0.y, bw1.y, 0x7632);
        o1.x = __byte_perm(bw0.z, bw1.z, 0x5410); o1.y = __byte_perm(bw0.z, bw1.z, 0x7632);
        o1.z = __byte_perm(bw0.w, bw1.w, 0x5410); o1.w = __byte_perm(bw0.w, bw1.w, 0x7632);
        *(uint4*)&d[0] = o0;
        *(uint4*)&d[4] = o1;
    };

    ldg_tiles(0);
    sts_tiles(0);
    __syncthreads();

    for (int kt = 0; kt < KT; kt++) {
        const int buf = kt & 1;
        if (kt + 1 < KT) ldg_tiles(kt + 1);

        const uint32_t* pA = sA[buf];
        const uint32_t* pB = sB[buf];
#pragma unroll
        for (int ks = 0; ks < 2; ks++) {
            uint32_t af[4][4], bfr[4][2];
#pragma unroll
            for (int mi = 0; mi < 4; mi++) {
                int row = warpM * 64 + mi * 16 + g;
                af[mi][0] = pA[row * RSA + ks * 8 + t];
                af[mi][1] = pA[(row + 8) * RSA + ks * 8 + t];
                af[mi][2] = pA[row * RSA + ks * 8 + t + 4];
                af[mi][3] = pA[(row + 8) * RSA + ks * 8 + t + 4];
            }
#pragma unroll
            for (int ni = 0; ni < 4; ni++) {
                int col = warpN * 32 + ni * 8 + g;
                bfr[ni][0] = pB[(ks * 8 + t) * RSB + col];
                bfr[ni][1] = pB[(ks * 8 + t + 4) * RSB + col];
            }
#pragma unroll
            for (int mi = 0; mi < 4; mi++)
#pragma unroll
                for (int ni = 0; ni < 4; ni++)
                    mma16816(acc[mi][ni], af[mi], bfr[ni]);
        }
        if (kt + 1 < KT) sts_tiles((kt + 1) & 1);
        __syncthreads();
    }

    // ---------------- epilogue ----------------
#pragma unroll
    for (int mi = 0; mi < 4; mi++) {
        size_t r0 = bm + warpM * 64 + mi * 16 + g;
#pragma unroll
        for (int ni = 0; ni < 4; ni++) {
            int col = bn + warpN * 32 + ni * 8 + 2 * t;
            float b0 = 0.f, b1 = 0.f;
            if (OUT != 4 && OUT != 5) {
                if (bias) { b0 = bias[col]; b1 = bias[col + 1]; }
            }
            // combine-mode per-column params (N == Q in these launches)
            float lin0 = 0.f, lin1 = 0.f, p30 = 0.f, p40 = 0.f, p50 = 0.f,
                  p31 = 0.f, p41 = 0.f, p51 = 0.f;
            if (OUT == 4 || OUT == 5) {
                lin0 = g_lin[li * Q + col];
                lin1 = g_lin[li * Q + col + 1];
                const float* pp0 = gparams + (size_t)(li * Q + col) * 6;
                const float* pp1 = pp0 + 6;
                p30 = pp0[3]; p40 = pp0[4]; p50 = pp0[5];
                p31 = pp1[3]; p41 = pp1[4]; p51 = pp1[5];
            }
#pragma unroll
            for (int half = 0; half < 2; half++) {
                size_t r = r0 + half * 8;
                float v0 = acc[mi][ni][half * 2 + 0] + b0;
                float v1 = acc[mi][ni][half * 2 + 1] + b1;
                if (ACT == 1) { v0 = v0 / (1.f + __expf(-v0)); v1 = v1 / (1.f + __expf(-v1)); }
                if (ACT == 2) { v0 = tanhf(v0); v1 = tanhf(v1); }
                size_t idx = r * (size_t)N + col;
                if (OUT == 0 || OUT == 2) { *(float2*)&Cf[idx] = make_float2(v0, v1); }
                if (OUT == 3) { Cf[idx] += scale * v0; Cf[idx + 1] += scale * v1; }
                if (OUT == 4 || OUT == 5) {
                    // v = entangled; c = current combined input
                    float c0 = Cf[idx], c1 = Cf[idx + 1];
                    float gate0 = (lin0 * c0 + 0.5f * __sinf(p30 * c0 + p40)
                                   + 0.5f * __cosf(p50 * c0)) * 0.25f;
                    float gate1 = (lin1 * c1 + 0.5f * __sinf(p31 * c1 + p41)
                                   + 0.5f * __cosf(p51 * c1)) * 0.25f;
                    float o0 = (c0 + 0.3f * gate0 + 0.2f * v0) * (1.f / 1.5f);
                    float o1 = (c1 + 0.3f * gate1 + 0.2f * v1) * (1.f / 1.5f);
                    Cf[idx] = o0; Cf[idx + 1] = o1;
                    if (OUT == 5) {
                        bf16 h0, l0, h1, l1;
                        split2(o0, h0, l0); split2(o1, h1, l1);
                        *(__nv_bfloat162*)&Chi[idx] = __nv_bfloat162(h0, h1);
                        *(__nv_bfloat162*)&Clo[idx] = __nv_bfloat162(l0, l1);
                    }
                }
                if (OUT == 1 || OUT == 2) {
                    bf16 h0, l0, h1, l1;
                    split2(v0, h0, l0); split2(v1, h1, l1);
                    *(__nv_bfloat162*)&Chi[idx] = __nv_bfloat162(h0, h1);
                    *(__nv_bfloat162*)&Clo[idx] = __nv_bfloat162(l0, l1);
                }
            }
        }
    }
}

template <int ACT, int OUT>
static void launch_mma(const bf16* Ahi, const bf16* Alo,
                       const bf16* Whi, const bf16* Wlo, const float* bias,
                       float* Cf, bf16* Chi, bf16* Clo, int N, int K,
                       float scale = 0.f, const float* gparams = nullptr, int li = 0)
{
    dim3 grid(N / BNT, B_SZ / BMT);
    mma_gemm<ACT, OUT><<<grid, 256>>>(Ahi, Alo, Whi, Wlo, bias, Cf, Chi, Clo,
                                      N, K, scale, gparams, li);
}

// ---------------- LayerNorm + exact GELU (row width 768) -> splits -----------
__global__ __launch_bounds__(256) void ln_gelu_kernel(
    const float* __restrict__ h, const float* __restrict__ w, const float* __restrict__ b,
    bf16* __restrict__ hhi, bf16* __restrict__ hlo)
{
    const size_t base = (size_t)blockIdx.x * Q3;
    const int t = threadIdx.x;
    float v0 = h[base + t], v1 = h[base + t + 256], v2 = h[base + t + 512];

    float s = blockReduce256(v0 + v1 + v2);
    float mu = s * (1.f / 768.f);
    float d0 = v0 - mu, d1 = v1 - mu, d2 = v2 - mu;
    float sq = blockReduce256(d0 * d0 + d1 * d1 + d2 * d2);
    float rstd = rsqrtf(sq * (1.f / 768.f) + 1e-5f);

#pragma unroll
    for (int e = 0; e < 3; e++) {
        int c = t + e * 256;
        float d = (e == 0) ? d0 : (e == 1) ? d1 : d2;
        float y = d * rstd * w[c] + b[c];
        y = 0.5f * y * (1.f + erff(y * 0.70710678118654752f));
        bf16 hi, lo; split2(y, hi, lo);
        hhi[base + c] = hi; hlo[base + c] = lo;
    }
}

// ---------------- residual mix + row L2 norm + tanh + splits -----------------
__global__ __launch_bounds__(256) void finalize_kernel(
    const float* __restrict__ res, float* __restrict__ out, float alpha, int write_split)
{
    size_t idx = (size_t)blockIdx.x * Q + threadIdx.x;
    float v = alpha * g_c2[idx] + (1.f - alpha) * res[idx];
    float sq = blockReduce256(v * v);
    float nrm = sqrtf(sq) + 1e-8f;
    float y = tanhf(v / nrm);
    out[idx] = y;
    if (write_split) {
        bf16 hi, lo; split2(y, hi, lo);
        s_curhi[idx] = hi; s_curlo[idx] = lo;
    }
}

// ---------------- fused weight prep (single launch) --------------------------
#define S0 (3 * Q * Q3)
#define S1 (3 * Q3 * Q)
#define S2 (3 * Q * Q2)
#define S3 (3 * Q2 * Q)
#define S4 (2 * Q * Q)
#define S5 (2 * Q * Q)
#define S6 (N_LAYERS * Q * Q)
#define S7 (4 * Q * Q)
#define S8 (4 * Q * Q)
#define WTOTAL (S0 + S1 + S2 + S3 + S4 + S5 + S6 + S7 + S8)

__global__ void prep_weights(
    const float* __restrict__ a0, const float* __restrict__ a1,
    const float* __restrict__ a2, const float* __restrict__ a3,
    const float* __restrict__ a4, const float* __restrict__ a5,
    const float* __restrict__ a6, const float* __restrict__ a7,
    const float* __restrict__ a8)
{
    int idx = blockIdx.x * 256 + threadIdx.x;
    float v; bf16* hi; bf16* lo; int local;
    if (idx < S0) {
        local = idx; v = a0[local]; hi = w0a_hi; lo = w0a_lo;
    } else if (idx < S0 + S1) {
        local = idx - S0; v = a1[local]; hi = w0b_hi; lo = w0b_lo;
    } else if (idx < S0 + S1 + S2) {
        local = idx - S0 - S1; v = a2[local]; hi = w1a_hi; lo = w1a_lo;
    } else if (idx < S0 + S1 + S2 + S3) {
        local = idx - S0 - S1 - S2; v = a3[local]; hi = w1b_hi; lo = w1b_lo;
    } else if (idx < S0 + S1 + S2 + S3 + S4) {
        local = idx - S0 - S1 - S2 - S3;
        int i = local >> 16, rem = local & 65535;
        int k = rem >> 8, c = rem & 255;
        v = a4[(size_t)i * Q * Q3 + (size_t)k * Q3 + 2 * Q + c];
        hi = wv_hi; lo = wv_lo;
    } else if (idx < S0 + S1 + S2 + S3 + S4 + S5) {
        local = idx - S0 - S1 - S2 - S3 - S4; v = a5[local]; hi = wo_hi; lo = wo_lo;
    } else if (idx < S0 + S1 + S2 + S3 + S4 + S5 + S6) {
        local = idx - S0 - S1 - S2 - S3 - S4 - S5; v = tanhf(a6[local]);
        hi = we_hi; lo = we_lo;
    } else if (idx < S0 + S1 + S2 + S3 + S4 + S5 + S6 + S7) {
        local = idx - S0 - S1 - S2 - S3 - S4 - S5 - S6; v = a7[local];
        hi = wn1_hi; lo = wn1_lo;
    } else {
        local = idx - S0 - S1 - S2 - S3 - S4 - S5 - S6 - S7; v = a8[local];
        hi = wn2_hi; lo = wn2_lo;
    }
    bf16 h, l; split2(v, h, l);
    hi[local] = h; lo[local] = l;
}

__global__ void prep_lin(const float* __restrict__ gp) {
    int idx = blockIdx.x * 256 + threadIdx.x;
    int li = idx / Q, q = idx % Q;
    const float* p = gp + (size_t)li * Q * 6 + q * 6;
    g_lin[idx] = sinf(p[0]) + cosf(p[1]) + tanhf(p[2]);
}

__global__ void split_plain(const float* __restrict__ src, bf16* __restrict__ hi,
                            bf16* __restrict__ lo) {
    size_t idx = (size_t)blockIdx.x * 256 + threadIdx.x;
    bf16 h, l; split2(src[idx], h, l);
    hi[idx] = h; lo[idx] = l;
}

// ---------------- orchestration ----------------------------------------------
extern "C" void kernel_launch(void* const* d_in, const int* in_sizes, int n_in,
                              void* d_out, int out_size)
{
    const float* x    = (const float*)d_in[0];
    const float* d0b1 = (const float*)d_in[2];
    const float* lnw  = (const float*)d_in[3];
    const float* lnb  = (const float*)d_in[4];
    const float* d0b2 = (const float*)d_in[6];
    const float* d1b1 = (const float*)d_in[8];
    const float* d1b2 = (const float*)d_in[10];
    const float* bqkv = (const float*)d_in[12];
    const float* bo   = (const float*)d_in[14];
    const float* gp   = (const float*)d_in[15];
    const float* nlb1 = (const float*)d_in[18];
    const float* nlb2 = (const float*)d_in[20];
    float* out = (float*)d_out;

    float *cur, *h, *c2;
    cudaGetSymbolAddress((void**)&cur, g_cur);
    cudaGetSymbolAddress((void**)&h,   g_h);
    cudaGetSymbolAddress((void**)&c2,  g_c2);

    bf16 *curhi, *curlo, *hhi, *hlo, *c2hi, *c2lo, *c3hi, *c3lo;
    cudaGetSymbolAddress((void**)&curhi, s_curhi);
    cudaGetSymbolAddress((void**)&curlo, s_curlo);
    cudaGetSymbolAddress((void**)&hhi,   s_hhi);
    cudaGetSymbolAddress((void**)&hlo,   s_hlo);
    cudaGetSymbolAddress((void**)&c2hi,  s_c2hi);
    cudaGetSymbolAddress((void**)&c2lo,  s_c2lo);
    cudaGetSymbolAddress((void**)&c3hi,  s_c3hi);
    cudaGetSymbolAddress((void**)&c3lo,  s_c3lo);

    bf16 *p_w0a_hi, *p_w0a_lo, *p_w0b_hi, *p_w0b_lo, *p_w1a_hi, *p_w1a_lo,
         *p_w1b_hi, *p_w1b_lo, *p_wv_hi, *p_wv_lo, *p_wo_hi, *p_wo_lo,
         *p_we_hi, *p_we_lo, *p_wn1_hi, *p_wn1_lo, *p_wn2_hi, *p_wn2_lo;
    cudaGetSymbolAddress((void**)&p_w0a_hi, w0a_hi); cudaGetSymbolAddress((void**)&p_w0a_lo, w0a_lo);
    cudaGetSymbolAddress((void**)&p_w0b_hi, w0b_hi); cudaGetSymbolAddress((void**)&p_w0b_lo, w0b_lo);
    cudaGetSymbolAddress((void**)&p_w1a_hi, w1a_hi); cudaGetSymbolAddress((void**)&p_w1a_lo, w1a_lo);
    cudaGetSymbolAddress((void**)&p_w1b_hi, w1b_hi); cudaGetSymbolAddress((void**)&p_w1b_lo, w1b_lo);
    cudaGetSymbolAddress((void**)&p_wv_hi,  wv_hi);  cudaGetSymbolAddress((void**)&p_wv_lo,  wv_lo);
    cudaGetSymbolAddress((void**)&p_wo_hi,  wo_hi);  cudaGetSymbolAddress((void**)&p_wo_lo,  wo_lo);
    cudaGetSymbolAddress((void**)&p_we_hi,  we_hi);  cudaGetSymbolAddress((void**)&p_we_lo,  we_lo);
    cudaGetSymbolAddress((void**)&p_wn1_hi, wn1_hi); cudaGetSymbolAddress((void**)&p_wn1_lo, wn1_lo);
    cudaGetSymbolAddress((void**)&p_wn2_hi, wn2_hi); cudaGetSymbolAddress((void**)&p_wn2_lo, wn2_lo);

    // launch 1: all weight splits fused
    prep_weights<<<WTOTAL / 256, 256>>>(
        (const float*)d_in[1], (const float*)d_in[5], (const float*)d_in[7],
        (const float*)d_in[9], (const float*)d_in[11], (const float*)d_in[13],
        (const float*)d_in[16], (const float*)d_in[17], (const float*)d_in[19]);
    // launch 2
    prep_lin<<<N_LAYERS * Q / 256, 256>>>(gp);
    // launch 3
    split_plain<<<(size_t)B_SZ * Q / 256, 256>>>(x, curhi, curlo);

    for (int li = 0; li < N_LAYERS; li++) {
        const int t = li % 3;

        if (t == 0) {
            int i = li / 3;
            launch_mma<0, 0>(curhi, curlo, p_w0a_hi + (size_t)i * Q * Q3, p_w0a_lo + (size_t)i * Q * Q3,
                             d0b1 + i * Q3, h, nullptr, nullptr, Q3, Q);
            ln_gelu_kernel<<<B_SZ, 256>>>(h, lnw + i * Q3, lnb + i * Q3, hhi, hlo);
            launch_mma<0, 2>(hhi, hlo, p_w0b_hi + (size_t)i * Q3 * Q, p_w0b_lo + (size_t)i * Q3 * Q,
                             d0b2 + i * Q, c2, c2hi, c2lo, Q, Q3);
        } else if (t == 1) {
            int i = (li - 1) / 3;
            launch_mma<1, 1>(curhi, curlo, p_w1a_hi + (size_t)i * Q * Q2, p_w1a_lo + (size_t)i * Q * Q2,
                             d1b1 + i * Q2, nullptr, hhi, hlo, Q2, Q);
            launch_mma<0, 2>(hhi, hlo, p_w1b_hi + (size_t)i * Q2 * Q, p_w1b_lo + (size_t)i * Q2 * Q,
                             d1b2 + i * Q, c2, c2hi, c2lo, Q, Q2);
        } else {
            int i = (li - 2) / 3;
            launch_mma<0, 1>(curhi, curlo, p_wv_hi + (size_t)i * Q * Q, p_wv_lo + (size_t)i * Q * Q,
                             bqkv + i * Q3 + 2 * Q, nullptr, hhi, hlo, Q, Q);
            launch_mma<0, 2>(hhi, hlo, p_wo_hi + (size_t)i * Q * Q, p_wo_lo + (size_t)i * Q * Q,
                             bo + i * Q, c2, c2hi, c2lo, Q, Q);
        }

        // ent GEMM with fused gate/entangle combine; splits (odd layers) go to
        // separate c3 buffers to avoid racing the in-flight A operand (c2 splits)
        if (li & 1)
            launch_mma<0, 5>(c2hi, c2lo, p_we_hi + (size_t)li * Q * Q, p_we_lo + (size_t)li * Q * Q,
                             nullptr, c2, c3hi, c3lo, Q, Q, 0.f, gp, li);
        else
            launch_mma<0, 4>(c2hi, c2lo, p_we_hi + (size_t)li * Q * Q, p_we_lo + (size_t)li * Q * Q,
                             nullptr, c2, nullptr, nullptr, Q, Q, 0.f, gp, li);

        if (li & 1) {
            int j = li / 2;
            launch_mma<2, 1>(c3hi, c3lo, p_wn1_hi + (size_t)j * Q * Q, p_wn1_lo + (size_t)j * Q * Q,
                             nlb1 + j * Q, nullptr, hhi, hlo, Q, Q);
            launch_mma<0, 3>(hhi, hlo, p_wn2_hi + (size_t)j * Q * Q, p_wn2_lo + (size_t)j * Q * Q,
                             nlb2 + j * Q, c2, nullptr, nullptr, Q, Q, 0.1f);
        }

        float alpha = (li < N_LAYERS / 2) ? 0.8f : 0.6f;
        finalize_kernel<<<B_SZ, 256>>>((li == 0) ? x : cur, (li == 7) ? out : cur,
                                       alpha, (li == 7) ? 0 : 1);
    }
}